// round 14
// baseline (speedup 1.0000x reference)
#include <cuda_runtime.h>
#include <cstdint>
#include <math.h>

// Problem constants
#define BDIM 4
#define SDIM 2048
#define DDIM 2048
#define HDIM 16
#define DKDIM 128
#define MDIM (BDIM * SDIM)   // 8192
#define GK 2048
#define GN 2048

#define NEGV (-1e9f)
#define SCALE 0.08838834764831845f  // 1/sqrt(128)

// Fragment-plane offsets
#define QLOFF 8388608ull       // u32 offset of lo plane (Q A-frag layout)
#define KLOFF 8388608ull       // u32 offset of lo plane (K B-frag layout)
#define QLOFF4 2097152ull      // same in uint4 units
#define KLOFF4 2097152ull
#define VLOFF4 2097152ull      // V-frag lo plane in uint4 units
#define VLOFF2 4194304u        // V-frag lo plane in uint2 units

// Scratch (device globals — no cudaMalloc allowed)
__device__ float g_Q[(size_t)MDIM * DDIM];     // Q in A-frag layout: hi|lo planes
__device__ float g_K[(size_t)MDIM * DDIM];     // K in B-frag layout: hi|lo planes
__device__ float g_V[(size_t)MDIM * DDIM];     // fp32 V row-major
__device__ uint32_t g_VF[16777216];            // V in PV B-frag layout: hi|lo planes
__device__ float g_att[(size_t)MDIM * DDIM];
__device__ float g_vmean[BDIM * HDIM * DKDIM];

// ---------------------------------------------------------------------------
__device__ __forceinline__ void mma_bf16_16x8x16(
    float* c, const uint32_t* a, uint32_t b0, uint32_t b1)
{
    asm volatile(
        "mma.sync.aligned.m16n8k16.row.col.f32.bf16.bf16.f32 "
        "{%0,%1,%2,%3}, {%4,%5,%6,%7}, {%8,%9}, {%0,%1,%2,%3};"
        : "+f"(c[0]), "+f"(c[1]), "+f"(c[2]), "+f"(c[3])
        : "r"(a[0]), "r"(a[1]), "r"(a[2]), "r"(a[3]), "r"(b0), "r"(b1));
}

__device__ __forceinline__ void split2(float x, float y, uint32_t& hi, uint32_t& lo)
{
    uint32_t bx = __float_as_uint(x), by = __float_as_uint(y);
    uint32_t hx = (bx + 0x7FFFu + ((bx >> 16) & 1u)) >> 16;
    uint32_t hy = (by + 0x7FFFu + ((by >> 16) & 1u)) >> 16;
    hi = hx | (hy << 16);
    float lx = x - __uint_as_float(hx << 16);
    float ly = y - __uint_as_float(hy << 16);
    uint32_t blx = __float_as_uint(lx), bly = __float_as_uint(ly);
    uint32_t hlx = (blx + 0x7FFFu + ((blx >> 16) & 1u)) >> 16;
    uint32_t hly = (bly + 0x7FFFu + ((bly >> 16) & 1u)) >> 16;
    lo = hlx | (hly << 16);
}

__device__ __forceinline__ float fexp(float x)
{
    float t = x * 1.4426950408889634f;
    t = fmaxf(t, -126.0f);
    float n = rintf(t);
    float f = t - n;
    float p = 0.0013333558f;
    p = fmaf(p, f, 0.0096181291f);
    p = fmaf(p, f, 0.0555041087f);
    p = fmaf(p, f, 0.2402265070f);
    p = fmaf(p, f, 0.6931471806f);
    p = fmaf(p, f, 1.0f);
    int e = (int)n;
    return __uint_as_float((uint32_t)((e + 127) << 23)) * p;
}

__device__ __forceinline__ uint32_t smem_u32(const void* p) {
    uint32_t a;
    asm("{ .reg .u64 t; cvta.to.shared.u64 t, %1; cvt.u32.u64 %0, t; }" : "=r"(a) : "l"(p));
    return a;
}

__device__ __forceinline__ void cp16(uint32_t dst, const void* src) {
    asm volatile("cp.async.ca.shared.global [%0], [%1], 16;" :: "r"(dst), "l"(src));
}
#define CPCOMMIT() asm volatile("cp.async.commit_group;" ::: "memory")
#define CPWAIT0()  asm volatile("cp.async.wait_group 0;" ::: "memory")

// ===========================================================================
// GEMM (TN) split-bf16. mode 0: fp32 out. mode 1: Q A-frag out. mode 2: K B-frag.
// ===========================================================================
__global__ void __launch_bounds__(256, 2) gemm_mma_kernel(
    const float* __restrict__ A, const float* __restrict__ W, void* __restrict__ Cv,
    int mode)
{
    __shared__ uint32_t Ahs[128][20];
    __shared__ uint32_t Als[128][20];
    __shared__ uint32_t Bhs[128][20];
    __shared__ uint32_t Bls[128][20];

    const int tid  = threadIdx.x;
    const int lane = tid & 31;
    const int w    = tid >> 5;
    const int wm   = (w & 3) * 32;
    const int wn   = (w >> 2) * 64;
    const int gid  = lane >> 2;
    const int tig  = lane & 3;
    const int bm   = blockIdx.y * 128;
    const int bn   = blockIdx.x * 128;

    const int r0   = tid >> 3;
    const int c0f  = (tid & 7) * 4;
    const int c0u  = (tid & 7) * 2;

    const float* Ap = A + (size_t)(bm + r0) * GK + c0f;
    const float* Wp = W + (size_t)(bn + r0) * GK + c0f;

    float acc[2][8][4];
#pragma unroll
    for (int mt = 0; mt < 2; mt++)
#pragma unroll
        for (int nt = 0; nt < 8; nt++)
#pragma unroll
            for (int q = 0; q < 4; q++) acc[mt][nt][q] = 0.f;

    for (int kc = 0; kc < GK / 32; kc++) {
        __syncthreads();
        const float* Ak = Ap + kc * 32;
        const float* Wk = Wp + kc * 32;
#pragma unroll
        for (int j = 0; j < 4; j++) {
            float4 a = *(const float4*)(Ak + (size_t)(32 * j) * GK);
            uint32_t h0, l0, h1, l1;
            split2(a.x, a.y, h0, l0); split2(a.z, a.w, h1, l1);
            *(uint2*)&Ahs[r0 + 32 * j][c0u] = make_uint2(h0, h1);
            *(uint2*)&Als[r0 + 32 * j][c0u] = make_uint2(l0, l1);
            float4 b = *(const float4*)(Wk + (size_t)(32 * j) * GK);
            split2(b.x, b.y, h0, l0); split2(b.z, b.w, h1, l1);
            *(uint2*)&Bhs[r0 + 32 * j][c0u] = make_uint2(h0, h1);
            *(uint2*)&Bls[r0 + 32 * j][c0u] = make_uint2(l0, l1);
        }
        __syncthreads();

#pragma unroll
        for (int ks = 0; ks < 2; ks++) {
            const int kb = ks * 8;
            uint32_t ah[2][4], al[2][4];
#pragma unroll
            for (int mt = 0; mt < 2; mt++) {
                const int rb = wm + mt * 16;
                ah[mt][0] = Ahs[rb + gid][kb + tig];
                ah[mt][1] = Ahs[rb + gid + 8][kb + tig];
                ah[mt][2] = Ahs[rb + gid][kb + tig + 4];
                ah[mt][3] = Ahs[rb + gid + 8][kb + tig + 4];
                al[mt][0] = Als[rb + gid][kb + tig];
                al[mt][1] = Als[rb + gid + 8][kb + tig];
                al[mt][2] = Als[rb + gid][kb + tig + 4];
                al[mt][3] = Als[rb + gid + 8][kb + tig + 4];
            }
#pragma unroll
            for (int nt = 0; nt < 8; nt++) {
                const int nb = wn + nt * 8 + gid;
                uint32_t bh0 = Bhs[nb][kb + tig], bh1 = Bhs[nb][kb + tig + 4];
                uint32_t bl0 = Bls[nb][kb + tig], bl1 = Bls[nb][kb + tig + 4];
                mma_bf16_16x8x16(acc[0][nt], ah[0], bh0, bh1);
                mma_bf16_16x8x16(acc[1][nt], ah[1], bh0, bh1);
                mma_bf16_16x8x16(acc[0][nt], ah[0], bl0, bl1);
                mma_bf16_16x8x16(acc[1][nt], ah[1], bl0, bl1);
                mma_bf16_16x8x16(acc[0][nt], al[0], bh0, bh1);
                mma_bf16_16x8x16(acc[1][nt], al[1], bh0, bh1);
            }
        }
    }

    if (mode == 0) {
        float* C = (float*)Cv;
#pragma unroll
        for (int mt = 0; mt < 2; mt++) {
            const int row = bm + wm + mt * 16 + gid;
#pragma unroll
            for (int nt = 0; nt < 8; nt++) {
                const int col = bn + wn + nt * 8 + tig * 2;
                *(float2*)(C + (size_t)row * GN + col) =
                    make_float2(acc[mt][nt][0], acc[mt][nt][1]);
                *(float2*)(C + (size_t)(row + 8) * GN + col) =
                    make_float2(acc[mt][nt][2], acc[mt][nt][3]);
            }
        }
    } else if (mode == 1) {
        uint32_t* U = (uint32_t*)Cv;
        const int hh = bn >> 7;
#pragma unroll
        for (int mt = 0; mt < 2; mt++) {
            const int rb = (bm >> 4) + (w & 3) * 2 + mt;
#pragma unroll
            for (int j = 0; j < 4; j++) {
                const int ks = (w >> 2) * 4 + j;
                uint32_t h0, l0, h1, l1, h2, l2, h3, l3;
                split2(acc[mt][2 * j][0], acc[mt][2 * j][1], h0, l0);
                split2(acc[mt][2 * j][2], acc[mt][2 * j][3], h1, l1);
                split2(acc[mt][2 * j + 1][0], acc[mt][2 * j + 1][1], h2, l2);
                split2(acc[mt][2 * j + 1][2], acc[mt][2 * j + 1][3], h3, l3);
                size_t idx = ((((size_t)rb * 16 + hh) * 8 + ks) * 32 + lane) * 4;
                *(uint4*)(U + idx) = make_uint4(h0, h1, h2, h3);
                *(uint4*)(U + QLOFF + idx) = make_uint4(l0, l1, l2, l3);
            }
        }
    } else {
        uint32_t* U = (uint32_t*)Cv;
        const int hh = bn >> 7;
#pragma unroll
        for (int mt = 0; mt < 2; mt++) {
            const int rb = (bm >> 4) + (w & 3) * 2 + mt;
#pragma unroll
            for (int j = 0; j < 4; j++) {
                const int ks = (w >> 2) * 4 + j;
                uint32_t h0, l0, h1, l1, h2, l2, h3, l3;
                split2(acc[mt][2 * j][0], acc[mt][2 * j][1], h0, l0);
                split2(acc[mt][2 * j][2], acc[mt][2 * j][3], h1, l1);
                split2(acc[mt][2 * j + 1][0], acc[mt][2 * j + 1][1], h2, l2);
                split2(acc[mt][2 * j + 1][2], acc[mt][2 * j + 1][3], h3, l3);
                size_t idx = ((((size_t)rb * 16 + hh) * 8 + ks) * 2) * 64 + lane * 2;
                *(uint2*)(U + idx) = make_uint2(h0, h2);
                *(uint2*)(U + KLOFF + idx) = make_uint2(l0, l2);
                *(uint2*)(U + idx + 64) = make_uint2(h1, h3);
                *(uint2*)(U + KLOFF + idx + 64) = make_uint2(l1, l3);
            }
        }
    }
}

// ---------------------------------------------------------------------------
__global__ void vmean_kernel(const float* __restrict__ Vg, float* __restrict__ vmean)
{
    __shared__ float red[8][128];
    int bh = blockIdx.x;
    int b = bh >> 4, h = bh & 15;
    int d = threadIdx.x & 127;
    int ch = threadIdx.x >> 7;
    const float* Vb = Vg + ((size_t)b * SDIM + ch * 256) * DDIM + h * DKDIM + d;
    float s = 0.f;
    for (int j = 0; j < 256; j++) s += Vb[(size_t)j * DDIM];
    red[ch][d] = s;
    __syncthreads();
    if (ch == 0) {
        float t = red[0][d] + red[1][d] + red[2][d] + red[3][d]
                + red[4][d] + red[5][d] + red[6][d] + red[7][d];
        vmean[bh * DKDIM + d] = t * (1.f / (float)SDIM);
    }
}

// ---------------------------------------------------------------------------
// V pre-split into PV B-fragment layout.
// ---------------------------------------------------------------------------
__global__ void vsplit_kernel(const float* __restrict__ Vg, uint32_t* __restrict__ VF)
{
    __shared__ float vs[16][132];
    const int h = blockIdx.x, kb = blockIdx.y, b = blockIdx.z;
    const int tid = threadIdx.x;  // 128

    const float* src = Vg + ((size_t)(b * SDIM + kb * 16)) * DDIM + h * DKDIM;
#pragma unroll
    for (int j = 0; j < 4; j++) {
        int idx = tid + j * 128;
        int r = idx >> 5, c4 = (idx & 31) * 4;
        *(float4*)&vs[r][c4] = *(const float4*)(src + (size_t)r * DDIM + c4);
    }
    __syncthreads();

    uint2* VF2 = (uint2*)VF;
    const uint32_t base = ((uint32_t)((b * 128 + kb) * 16 + h)) * 512;
#pragma unroll
    for (int j = 0; j < 4; j++) {
        int i = tid + j * 128;
        int nb = i >> 5, lane = i & 31, gid = lane >> 2, tig = lane & 3;
        int d = nb * 8 + gid;
        uint32_t b0h, b0l, b1h, b1l;
        split2(vs[2 * tig][d],     vs[2 * tig + 1][d], b0h, b0l);
        split2(vs[2 * tig + 8][d], vs[2 * tig + 9][d], b1h, b1l);
        VF2[base + i] = make_uint2(b0h, b1h);
        VF2[VLOFF2 + base + i] = make_uint2(b0l, b1l);
    }
}

// ===========================================================================
// Flash attention, q-tile 128, 512 threads (16 warps = 8 qb x 2 dh), 1 CTA/SM.
// Double-buffered K/V/mask via cp.async; prefetch kt+1 overlaps compute of kt.
// SMEM u32: Q[0,16384) | K stage s at 16384+s*8192 (hi 4K, lo 4K; P overlays)
//           V stage s at 32768+s*8192 | pmx[49152] pls[49408] mask[49664]
// ===========================================================================
#define AQ 0
#define AQL 8192
#define AKST(s) (16384 + (s) * 8192)
#define AVST(s) (32768 + (s) * 8192)
#define APMX 49152
#define APLS 49408
#define AMSK 49664
#define ATT_U32 49792
#define ATT_SMEM_BYTES (ATT_U32 * 4)   // 199168

__global__ void __launch_bounds__(512, 1) attn_mma_kernel(
    const uint4* __restrict__ Qf4, const uint4* __restrict__ Kf4,
    const uint4* __restrict__ VF4, const int* __restrict__ maskg,
    const float* __restrict__ vmean, float* __restrict__ Og)
{
    extern __shared__ uint32_t smu[];
    float* pmxF = (float*)(smu + APMX);   // [2][128]
    float* plsF = (float*)(smu + APLS);   // [2][128]
    int* maskS  = (int*)(smu + AMSK);     // [2][64]
    const uint32_t sb = smem_u32(smu);

    const int qt = (int)gridDim.x - 1 - (int)blockIdx.x;  // longest first
    const int h = blockIdx.y, b = blockIdx.z;
    const int tid = threadIdx.x, lane = tid & 31, w = tid >> 5;
    const int gid = lane >> 2, tig = lane & 3;
    const int qb = w & 7, dh = w >> 3;
    const int q0 = qt * 128;
    const int r1 = qb * 16 + gid, r2 = r1 + 8;

    const int* mb = maskg + b * SDIM;

    // Stage Q (64 KB) + stage 0 K/V/mask in one cp.async group
    for (int i = tid; i < 2048; i += 512) {
        int qbl = i >> 8, j = i & 255;
        size_t src = ((size_t)(b * 128 + qt * 8 + qbl) * 16 + h) * 256 + j;
        cp16(sb + AQ * 4 + i * 16, Qf4 + src);
        cp16(sb + AQL * 4 + i * 16, Qf4 + QLOFF4 + src);
    }
    for (int i = tid; i < 1024; i += 512) {
        int rbl = i >> 8, j = i & 255;
        size_t srcK = ((size_t)(b * 128 + 0 * 4 + rbl) * 16 + h) * 256 + j;
        cp16(sb + AKST(0) * 4 + i * 16, Kf4 + srcK);
        cp16(sb + (AKST(0) + 4096) * 4 + i * 16, Kf4 + KLOFF4 + srcK);
        cp16(sb + AVST(0) * 4 + i * 16, VF4 + srcK);
        cp16(sb + (AVST(0) + 4096) * 4 + i * 16, VF4 + VLOFF4 + srcK);
    }
    if (tid < 16) cp16(sb + AMSK * 4 + tid * 16, mb + tid * 4);
    CPCOMMIT();

    float m1 = -3.402823466e38f, m2 = -3.402823466e38f;
    float l1 = 0.f, l2 = 0.f;
    float o[8][4];
#pragma unroll
    for (int nt = 0; nt < 8; nt++)
#pragma unroll
        for (int q = 0; q < 4; q++) o[nt][q] = 0.f;

    const int nkt = 2 * qt + 2;
    for (int kt = 0; kt < nkt; kt++) {
        const int s = kt & 1;
        const int k0 = kt * 64;
        CPWAIT0();          // stage(kt) (+Q on kt=0) landed
        __syncthreads();    // all warps past prev iter's buffer reads

        // Prefetch stage(kt+1) into the other buffer — overlaps compute below
        if (kt + 1 < nkt) {
            const int sn = s ^ 1, ktn = kt + 1;
            for (int i = tid; i < 1024; i += 512) {
                int rbl = i >> 8, j = i & 255;
                size_t srcK = ((size_t)(b * 128 + ktn * 4 + rbl) * 16 + h) * 256 + j;
                cp16(sb + AKST(sn) * 4 + i * 16, Kf4 + srcK);
                cp16(sb + (AKST(sn) + 4096) * 4 + i * 16, Kf4 + KLOFF4 + srcK);
                cp16(sb + AVST(sn) * 4 + i * 16, VF4 + srcK);
                cp16(sb + (AVST(sn) + 4096) * 4 + i * 16, VF4 + VLOFF4 + srcK);
            }
            if (tid < 16) cp16(sb + (AMSK + 64) * 4 - s * 256 + tid * 16,
                               mb + ktn * 64 + tid * 4);
        }
        CPCOMMIT();

        const int AK_ = AKST(s);
        const int AV_ = AVST(s);

        // QK: dual accumulation chains
        float sc[4][4], scB[4][4];
#pragma unroll
        for (int nt = 0; nt < 4; nt++)
#pragma unroll
            for (int q = 0; q < 4; q++) { sc[nt][q] = 0.f; scB[nt][q] = 0.f; }

#pragma unroll
        for (int ks = 0; ks < 8; ks++) {
            uint4 ahv = *(const uint4*)&smu[AQ + ((qb * 8 + ks) * 32 + lane) * 4];
            uint4 alv = *(const uint4*)&smu[AQL + ((qb * 8 + ks) * 32 + lane) * 4];
            uint32_t ah[4] = {ahv.x, ahv.y, ahv.z, ahv.w};
            uint32_t al[4] = {alv.x, alv.y, alv.z, alv.w};
            float (*acc)[4] = (ks < 4) ? sc : scB;
#pragma unroll
            for (int nt = 0; nt < 4; nt++) {
                const int ntg = dh * 4 + nt;
                const int base = AK_ + (((ntg >> 1) * 8 + ks) * 2 + (ntg & 1)) * 64 + lane * 2;
                uint2 kh = *(const uint2*)&smu[base];
                uint2 kl = *(const uint2*)&smu[base + 4096];
                mma_bf16_16x8x16(acc[nt], ah, kh.x, kh.y);
                mma_bf16_16x8x16(acc[nt], ah, kl.x, kl.y);
                mma_bf16_16x8x16(acc[nt], al, kh.x, kh.y);
            }
        }
#pragma unroll
        for (int nt = 0; nt < 4; nt++)
#pragma unroll
            for (int q = 0; q < 4; q++) sc[nt][q] += scB[nt][q];

        // Mask + scale + per-half tile max
        float tm1 = -3.402823466e38f, tm2 = -3.402823466e38f;
#pragma unroll
        for (int nt = 0; nt < 4; nt++) {
#pragma unroll
            for (int jj = 0; jj < 2; jj++) {
                const int col = dh * 32 + nt * 8 + tig * 2 + jj;
                const int jg = k0 + col;
                const bool ok = (maskS[s * 64 + col] != 0);
                float s0 = (ok && jg <= q0 + r1) ? sc[nt][jj] * SCALE : NEGV;
                float s1 = (ok && jg <= q0 + r2) ? sc[nt][2 + jj] * SCALE : NEGV;
                sc[nt][jj] = s0; sc[nt][2 + jj] = s1;
                tm1 = fmaxf(tm1, s0); tm2 = fmaxf(tm2, s1);
            }
        }
        tm1 = fmaxf(tm1, __shfl_xor_sync(0xffffffffu, tm1, 1));
        tm1 = fmaxf(tm1, __shfl_xor_sync(0xffffffffu, tm1, 2));
        tm2 = fmaxf(tm2, __shfl_xor_sync(0xffffffffu, tm2, 1));
        tm2 = fmaxf(tm2, __shfl_xor_sync(0xffffffffu, tm2, 2));
        if (tig == 0) { pmxF[dh * 128 + r1] = tm1; pmxF[dh * 128 + r2] = tm2; }
        __syncthreads();  // pmx ready; K(s) reads done -> region reusable for P

        const float mn1 = fmaxf(m1, fmaxf(pmxF[r1], pmxF[128 + r1]));
        const float mn2 = fmaxf(m2, fmaxf(pmxF[r2], pmxF[128 + r2]));
        const float c1 = fexp(m1 - mn1), c2 = fexp(m2 - mn2);
        m1 = mn1; m2 = mn2;

        float s1sum = 0.f, s2sum = 0.f;
#pragma unroll
        for (int nt = 0; nt < 4; nt++) {
            sc[nt][0] = fexp(sc[nt][0] - mn1);
            sc[nt][1] = fexp(sc[nt][1] - mn1);
            sc[nt][2] = fexp(sc[nt][2] - mn2);
            sc[nt][3] = fexp(sc[nt][3] - mn2);
            s1sum += sc[nt][0] + sc[nt][1];
            s2sum += sc[nt][2] + sc[nt][3];
        }
        s1sum += __shfl_xor_sync(0xffffffffu, s1sum, 1);
        s1sum += __shfl_xor_sync(0xffffffffu, s1sum, 2);
        s2sum += __shfl_xor_sync(0xffffffffu, s2sum, 1);
        s2sum += __shfl_xor_sync(0xffffffffu, s2sum, 2);
        if (tig == 0) { plsF[dh * 128 + r1] = s1sum; plsF[dh * 128 + r2] = s2sum; }

        // Write P A-frags into retired K(s) region (hi at AK_, lo at AK_+4096)
#pragma unroll
        for (int t = 0; t < 2; t++) {
            const int ks2 = dh * 2 + t;
            uint32_t h0, l0, h1, l1u, h2, l2u, h3, l3;
            split2(sc[2 * t][0], sc[2 * t][1], h0, l0);
            split2(sc[2 * t][2], sc[2 * t][3], h1, l1u);
            split2(sc[2 * t + 1][0], sc[2 * t + 1][1], h2, l2u);
            split2(sc[2 * t + 1][2], sc[2 * t + 1][3], h3, l3);
            const int idx = ((qb * 4 + ks2) * 32 + lane) * 4;
            *(uint4*)&smu[AK_ + idx] = make_uint4(h0, h1, h2, h3);
            *(uint4*)&smu[AK_ + 4096 + idx] = make_uint4(l0, l1u, l2u, l3);
        }
        __syncthreads();  // P + pls visible

        l1 = l1 * c1 + plsF[r1] + plsF[128 + r1];
        l2 = l2 * c2 + plsF[r2] + plsF[128 + r2];

#pragma unroll
        for (int nt = 0; nt < 8; nt++) {
            o[nt][0] *= c1; o[nt][1] *= c1; o[nt][2] *= c2; o[nt][3] *= c2;
        }

        // PV: A = P frags, B = pre-split V frags
#pragma unroll
        for (int ks2 = 0; ks2 < 4; ks2++) {
            const int idx = ((qb * 4 + ks2) * 32 + lane) * 4;
            uint4 phv = *(const uint4*)&smu[AK_ + idx];
            uint4 plv = *(const uint4*)&smu[AK_ + 4096 + idx];
            uint32_t ph[4] = {phv.x, phv.y, phv.z, phv.w};
            uint32_t pl[4] = {plv.x, plv.y, plv.z, plv.w};
#pragma unroll
            for (int nt = 0; nt < 8; nt++) {
                const int vi = AV_ + ks2 * 1024 + (dh * 8 + nt) * 64 + lane * 2;
                uint2 vh = *(const uint2*)&smu[vi];
                uint2 vl = *(const uint2*)&smu[vi + 4096];
                mma_bf16_16x8x16(o[nt], ph, vh.x, vh.y);
                mma_bf16_16x8x16(o[nt], ph, vl.x, vl.y);
                mma_bf16_16x8x16(o[nt], pl, vh.x, vh.y);
            }
        }
    }

    // Epilogue
    const float inv1 = 1.f / l1, inv2 = 1.f / l2;
    const bool dead1 = m1 < -1e8f, dead2 = m2 < -1e8f;
    const float* vm = vmean + ((size_t)b * HDIM + h) * DKDIM;
    float* O1 = Og + ((size_t)b * SDIM + q0 + r1) * DDIM + h * DKDIM;
    float* O2 = Og + ((size_t)b * SDIM + q0 + r2) * DDIM + h * DKDIM;
#pragma unroll
    for (int nt = 0; nt < 8; nt++) {
        const int d = dh * 64 + nt * 8 + tig * 2;
        float2 u1 = dead1 ? make_float2(vm[d], vm[d + 1])
                          : make_float2(o[nt][0] * inv1, o[nt][1] * inv1);
        float2 u2 = dead2 ? make_float2(vm[d], vm[d + 1])
                          : make_float2(o[nt][2] * inv2, o[nt][3] * inv2);
        *(float2*)(O1 + d) = u1;
        *(float2*)(O2 + d) = u2;
    }
}

// ---------------------------------------------------------------------------
extern "C" void kernel_launch(void* const* d_in, const int* in_sizes, int n_in,
                              void* d_out, int out_size)
{
    const float* x    = (const float*)d_in[0];
    const int*   mask = (const int*)d_in[1];
    const float* wq   = (const float*)d_in[2];
    const float* wk   = (const float*)d_in[3];
    const float* wv   = (const float*)d_in[4];
    const float* wo   = (const float*)d_in[5];
    float* out = (float*)d_out;

    float *pQ, *pK, *pV, *pAtt, *pVm;
    uint32_t* pVF;
    cudaGetSymbolAddress((void**)&pQ, g_Q);
    cudaGetSymbolAddress((void**)&pK, g_K);
    cudaGetSymbolAddress((void**)&pV, g_V);
    cudaGetSymbolAddress((void**)&pVF, g_VF);
    cudaGetSymbolAddress((void**)&pAtt, g_att);
    cudaGetSymbolAddress((void**)&pVm, g_vmean);

    cudaFuncSetAttribute(attn_mma_kernel, cudaFuncAttributeMaxDynamicSharedMemorySize,
                         ATT_SMEM_BYTES);

    dim3 gg(GN / 128, MDIM / 128);  // (16, 64)
    gemm_mma_kernel<<<gg, 256>>>(x, wq, pQ, 1);   // Q -> A-frag layout
    gemm_mma_kernel<<<gg, 256>>>(x, wk, pK, 2);   // K -> B-frag layout
    gemm_mma_kernel<<<gg, 256>>>(x, wv, pV, 0);   // V fp32

    vmean_kernel<<<BDIM * HDIM, 1024>>>(pV, pVm);
    vsplit_kernel<<<dim3(HDIM, SDIM / 16, BDIM), 128>>>(pV, pVF);

    attn_mma_kernel<<<dim3(SDIM / 128, HDIM, BDIM), 512, ATT_SMEM_BYTES>>>(
        (const uint4*)pQ, (const uint4*)pK, (const uint4*)pVF, mask, pVm, pAtt);

    gemm_mma_kernel<<<gg, 256>>>(pAtt, wo, out, 0);
}

// round 15
// speedup vs baseline: 1.0031x; 1.0031x over previous
#include <cuda_runtime.h>
#include <cstdint>
#include <math.h>

// Problem constants
#define BDIM 4
#define SDIM 2048
#define DDIM 2048
#define HDIM 16
#define DKDIM 128
#define MDIM (BDIM * SDIM)   // 8192
#define GK 2048
#define GN 2048

#define NEGV (-1e9f)
#define SCALE 0.08838834764831845f  // 1/sqrt(128)

// Fragment-plane offsets
#define QLOFF 8388608ull       // u32 offset of lo plane (Q A-frag layout)
#define KLOFF 8388608ull       // u32 offset of lo plane (K B-frag layout)
#define QLOFF4 2097152ull      // same in uint4 units
#define KLOFF4 2097152ull
#define VLOFF4 2097152ull      // V-frag lo plane in uint4 units
#define VLOFF2 4194304u        // V-frag lo plane in uint2 units

// Scratch (device globals — no cudaMalloc allowed)
__device__ float g_Q[(size_t)MDIM * DDIM];     // Q in A-frag layout: hi|lo planes
__device__ float g_K[(size_t)MDIM * DDIM];     // K in B-frag layout: hi|lo planes
__device__ float g_V[(size_t)MDIM * DDIM];     // fp32 V row-major
__device__ uint32_t g_VF[16777216];            // V in PV B-frag layout: hi|lo planes
__device__ float g_att[(size_t)MDIM * DDIM];
__device__ float g_vmean[BDIM * HDIM * DKDIM];

// ---------------------------------------------------------------------------
__device__ __forceinline__ void mma_bf16_16x8x16(
    float* c, const uint32_t* a, uint32_t b0, uint32_t b1)
{
    asm volatile(
        "mma.sync.aligned.m16n8k16.row.col.f32.bf16.bf16.f32 "
        "{%0,%1,%2,%3}, {%4,%5,%6,%7}, {%8,%9}, {%0,%1,%2,%3};"
        : "+f"(c[0]), "+f"(c[1]), "+f"(c[2]), "+f"(c[3])
        : "r"(a[0]), "r"(a[1]), "r"(a[2]), "r"(a[3]), "r"(b0), "r"(b1));
}

__device__ __forceinline__ void split2(float x, float y, uint32_t& hi, uint32_t& lo)
{
    uint32_t bx = __float_as_uint(x), by = __float_as_uint(y);
    uint32_t hx = (bx + 0x7FFFu + ((bx >> 16) & 1u)) >> 16;
    uint32_t hy = (by + 0x7FFFu + ((by >> 16) & 1u)) >> 16;
    hi = hx | (hy << 16);
    float lx = x - __uint_as_float(hx << 16);
    float ly = y - __uint_as_float(hy << 16);
    uint32_t blx = __float_as_uint(lx), bly = __float_as_uint(ly);
    uint32_t hlx = (blx + 0x7FFFu + ((blx >> 16) & 1u)) >> 16;
    uint32_t hly = (bly + 0x7FFFu + ((bly >> 16) & 1u)) >> 16;
    lo = hlx | (hly << 16);
}

__device__ __forceinline__ float fexp(float x)
{
    float t = x * 1.4426950408889634f;
    t = fmaxf(t, -126.0f);
    float n = rintf(t);
    float f = t - n;
    float p = 0.0013333558f;
    p = fmaf(p, f, 0.0096181291f);
    p = fmaf(p, f, 0.0555041087f);
    p = fmaf(p, f, 0.2402265070f);
    p = fmaf(p, f, 0.6931471806f);
    p = fmaf(p, f, 1.0f);
    int e = (int)n;
    return __uint_as_float((uint32_t)((e + 127) << 23)) * p;
}

__device__ __forceinline__ uint32_t smem_u32(const void* p) {
    uint32_t a;
    asm("{ .reg .u64 t; cvta.to.shared.u64 t, %1; cvt.u32.u64 %0, t; }" : "=r"(a) : "l"(p));
    return a;
}

__device__ __forceinline__ void cp16(uint32_t dst, const void* src) {
    asm volatile("cp.async.ca.shared.global [%0], [%1], 16;" :: "r"(dst), "l"(src));
}
#define CPCOMMIT() asm volatile("cp.async.commit_group;" ::: "memory")
#define CPWAIT0()  asm volatile("cp.async.wait_group 0;" ::: "memory")

// ===========================================================================
// GEMM (TN) split-bf16. mode 0: fp32 out. mode 1: Q A-frag out. mode 2: K B-frag.
// ===========================================================================
__global__ void __launch_bounds__(256, 2) gemm_mma_kernel(
    const float* __restrict__ A, const float* __restrict__ W, void* __restrict__ Cv,
    int mode)
{
    __shared__ uint32_t Ahs[128][20];
    __shared__ uint32_t Als[128][20];
    __shared__ uint32_t Bhs[128][20];
    __shared__ uint32_t Bls[128][20];

    const int tid  = threadIdx.x;
    const int lane = tid & 31;
    const int w    = tid >> 5;
    const int wm   = (w & 3) * 32;
    const int wn   = (w >> 2) * 64;
    const int gid  = lane >> 2;
    const int tig  = lane & 3;
    const int bm   = blockIdx.y * 128;
    const int bn   = blockIdx.x * 128;

    const int r0   = tid >> 3;
    const int c0f  = (tid & 7) * 4;
    const int c0u  = (tid & 7) * 2;

    const float* Ap = A + (size_t)(bm + r0) * GK + c0f;
    const float* Wp = W + (size_t)(bn + r0) * GK + c0f;

    float acc[2][8][4];
#pragma unroll
    for (int mt = 0; mt < 2; mt++)
#pragma unroll
        for (int nt = 0; nt < 8; nt++)
#pragma unroll
            for (int q = 0; q < 4; q++) acc[mt][nt][q] = 0.f;

    for (int kc = 0; kc < GK / 32; kc++) {
        __syncthreads();
        const float* Ak = Ap + kc * 32;
        const float* Wk = Wp + kc * 32;
#pragma unroll
        for (int j = 0; j < 4; j++) {
            float4 a = *(const float4*)(Ak + (size_t)(32 * j) * GK);
            uint32_t h0, l0, h1, l1;
            split2(a.x, a.y, h0, l0); split2(a.z, a.w, h1, l1);
            *(uint2*)&Ahs[r0 + 32 * j][c0u] = make_uint2(h0, h1);
            *(uint2*)&Als[r0 + 32 * j][c0u] = make_uint2(l0, l1);
            float4 b = *(const float4*)(Wk + (size_t)(32 * j) * GK);
            split2(b.x, b.y, h0, l0); split2(b.z, b.w, h1, l1);
            *(uint2*)&Bhs[r0 + 32 * j][c0u] = make_uint2(h0, h1);
            *(uint2*)&Bls[r0 + 32 * j][c0u] = make_uint2(l0, l1);
        }
        __syncthreads();

#pragma unroll
        for (int ks = 0; ks < 2; ks++) {
            const int kb = ks * 8;
            uint32_t ah[2][4], al[2][4];
#pragma unroll
            for (int mt = 0; mt < 2; mt++) {
                const int rb = wm + mt * 16;
                ah[mt][0] = Ahs[rb + gid][kb + tig];
                ah[mt][1] = Ahs[rb + gid + 8][kb + tig];
                ah[mt][2] = Ahs[rb + gid][kb + tig + 4];
                ah[mt][3] = Ahs[rb + gid + 8][kb + tig + 4];
                al[mt][0] = Als[rb + gid][kb + tig];
                al[mt][1] = Als[rb + gid + 8][kb + tig];
                al[mt][2] = Als[rb + gid][kb + tig + 4];
                al[mt][3] = Als[rb + gid + 8][kb + tig + 4];
            }
#pragma unroll
            for (int nt = 0; nt < 8; nt++) {
                const int nb = wn + nt * 8 + gid;
                uint32_t bh0 = Bhs[nb][kb + tig], bh1 = Bhs[nb][kb + tig + 4];
                uint32_t bl0 = Bls[nb][kb + tig], bl1 = Bls[nb][kb + tig + 4];
                mma_bf16_16x8x16(acc[0][nt], ah[0], bh0, bh1);
                mma_bf16_16x8x16(acc[1][nt], ah[1], bh0, bh1);
                mma_bf16_16x8x16(acc[0][nt], ah[0], bl0, bl1);
                mma_bf16_16x8x16(acc[1][nt], ah[1], bl0, bl1);
                mma_bf16_16x8x16(acc[0][nt], al[0], bh0, bh1);
                mma_bf16_16x8x16(acc[1][nt], al[1], bh0, bh1);
            }
        }
    }

    if (mode == 0) {
        float* C = (float*)Cv;
#pragma unroll
        for (int mt = 0; mt < 2; mt++) {
            const int row = bm + wm + mt * 16 + gid;
#pragma unroll
            for (int nt = 0; nt < 8; nt++) {
                const int col = bn + wn + nt * 8 + tig * 2;
                *(float2*)(C + (size_t)row * GN + col) =
                    make_float2(acc[mt][nt][0], acc[mt][nt][1]);
                *(float2*)(C + (size_t)(row + 8) * GN + col) =
                    make_float2(acc[mt][nt][2], acc[mt][nt][3]);
            }
        }
    } else if (mode == 1) {
        uint32_t* U = (uint32_t*)Cv;
        const int hh = bn >> 7;
#pragma unroll
        for (int mt = 0; mt < 2; mt++) {
            const int rb = (bm >> 4) + (w & 3) * 2 + mt;
#pragma unroll
            for (int j = 0; j < 4; j++) {
                const int ks = (w >> 2) * 4 + j;
                uint32_t h0, l0, h1, l1, h2, l2, h3, l3;
                split2(acc[mt][2 * j][0], acc[mt][2 * j][1], h0, l0);
                split2(acc[mt][2 * j][2], acc[mt][2 * j][3], h1, l1);
                split2(acc[mt][2 * j + 1][0], acc[mt][2 * j + 1][1], h2, l2);
                split2(acc[mt][2 * j + 1][2], acc[mt][2 * j + 1][3], h3, l3);
                size_t idx = ((((size_t)rb * 16 + hh) * 8 + ks) * 32 + lane) * 4;
                *(uint4*)(U + idx) = make_uint4(h0, h1, h2, h3);
                *(uint4*)(U + QLOFF + idx) = make_uint4(l0, l1, l2, l3);
            }
        }
    } else {
        uint32_t* U = (uint32_t*)Cv;
        const int hh = bn >> 7;
#pragma unroll
        for (int mt = 0; mt < 2; mt++) {
            const int rb = (bm >> 4) + (w & 3) * 2 + mt;
#pragma unroll
            for (int j = 0; j < 4; j++) {
                const int ks = (w >> 2) * 4 + j;
                uint32_t h0, l0, h1, l1, h2, l2, h3, l3;
                split2(acc[mt][2 * j][0], acc[mt][2 * j][1], h0, l0);
                split2(acc[mt][2 * j][2], acc[mt][2 * j][3], h1, l1);
                split2(acc[mt][2 * j + 1][0], acc[mt][2 * j + 1][1], h2, l2);
                split2(acc[mt][2 * j + 1][2], acc[mt][2 * j + 1][3], h3, l3);
                size_t idx = ((((size_t)rb * 16 + hh) * 8 + ks) * 2) * 64 + lane * 2;
                *(uint2*)(U + idx) = make_uint2(h0, h2);
                *(uint2*)(U + KLOFF + idx) = make_uint2(l0, l2);
                *(uint2*)(U + idx + 64) = make_uint2(h1, h3);
                *(uint2*)(U + KLOFF + idx + 64) = make_uint2(l1, l3);
            }
        }
    }
}

// ---------------------------------------------------------------------------
__global__ void vmean_kernel(const float* __restrict__ Vg, float* __restrict__ vmean)
{
    __shared__ float red[8][128];
    int bh = blockIdx.x;
    int b = bh >> 4, h = bh & 15;
    int d = threadIdx.x & 127;
    int ch = threadIdx.x >> 7;
    const float* Vb = Vg + ((size_t)b * SDIM + ch * 256) * DDIM + h * DKDIM + d;
    float s = 0.f;
    for (int j = 0; j < 256; j++) s += Vb[(size_t)j * DDIM];
    red[ch][d] = s;
    __syncthreads();
    if (ch == 0) {
        float t = red[0][d] + red[1][d] + red[2][d] + red[3][d]
                + red[4][d] + red[5][d] + red[6][d] + red[7][d];
        vmean[bh * DKDIM + d] = t * (1.f / (float)SDIM);
    }
}

// ---------------------------------------------------------------------------
// V pre-split into PV B-fragment layout.
// ---------------------------------------------------------------------------
__global__ void vsplit_kernel(const float* __restrict__ Vg, uint32_t* __restrict__ VF)
{
    __shared__ float vs[16][132];
    const int h = blockIdx.x, kb = blockIdx.y, b = blockIdx.z;
    const int tid = threadIdx.x;  // 128

    const float* src = Vg + ((size_t)(b * SDIM + kb * 16)) * DDIM + h * DKDIM;
#pragma unroll
    for (int j = 0; j < 4; j++) {
        int idx = tid + j * 128;
        int r = idx >> 5, c4 = (idx & 31) * 4;
        *(float4*)&vs[r][c4] = *(const float4*)(src + (size_t)r * DDIM + c4);
    }
    __syncthreads();

    uint2* VF2 = (uint2*)VF;
    const uint32_t base = ((uint32_t)((b * 128 + kb) * 16 + h)) * 512;
#pragma unroll
    for (int j = 0; j < 4; j++) {
        int i = tid + j * 128;
        int nb = i >> 5, lane = i & 31, gid = lane >> 2, tig = lane & 3;
        int d = nb * 8 + gid;
        uint32_t b0h, b0l, b1h, b1l;
        split2(vs[2 * tig][d],     vs[2 * tig + 1][d], b0h, b0l);
        split2(vs[2 * tig + 8][d], vs[2 * tig + 9][d], b1h, b1l);
        VF2[base + i] = make_uint2(b0h, b1h);
        VF2[VLOFF2 + base + i] = make_uint2(b0l, b1l);
    }
}

// ===========================================================================
// Flash attention, q-tile 128, 512 threads (16 warps = 8 qb x 2 dh), 1 CTA/SM.
// Double-buffered K/V/mask via cp.async; prefetch kt+1 overlaps compute of kt.
// SMEM u32: Q[0,16384) | K stage s at 16384+s*8192 (hi 4K, lo 4K; P overlays)
//           V stage s at 32768+s*8192 | pmx[49152] pls[49408] mask[49664]
// ===========================================================================
#define AQ 0
#define AQL 8192
#define AKST(s) (16384 + (s) * 8192)
#define AVST(s) (32768 + (s) * 8192)
#define APMX 49152
#define APLS 49408
#define AMSK 49664
#define ATT_U32 49792
#define ATT_SMEM_BYTES (ATT_U32 * 4)   // 199168

__global__ void __launch_bounds__(512, 1) attn_mma_kernel(
    const uint4* __restrict__ Qf4, const uint4* __restrict__ Kf4,
    const uint4* __restrict__ VF4, const int* __restrict__ maskg,
    const float* __restrict__ vmean, float* __restrict__ Og)
{
    extern __shared__ uint32_t smu[];
    float* pmxF = (float*)(smu + APMX);   // [2][128]
    float* plsF = (float*)(smu + APLS);   // [2][128]
    int* maskS  = (int*)(smu + AMSK);     // [2][64]
    const uint32_t sb = smem_u32(smu);

    const int qt = (int)gridDim.x - 1 - (int)blockIdx.x;  // longest first
    const int h = blockIdx.y, b = blockIdx.z;
    const int tid = threadIdx.x, lane = tid & 31, w = tid >> 5;
    const int gid = lane >> 2, tig = lane & 3;
    const int qb = w & 7, dh = w >> 3;
    const int q0 = qt * 128;
    const int r1 = qb * 16 + gid, r2 = r1 + 8;

    const int* mb = maskg + b * SDIM;

    // Stage Q (64 KB) + stage 0 K/V/mask in one cp.async group
    for (int i = tid; i < 2048; i += 512) {
        int qbl = i >> 8, j = i & 255;
        size_t src = ((size_t)(b * 128 + qt * 8 + qbl) * 16 + h) * 256 + j;
        cp16(sb + AQ * 4 + i * 16, Qf4 + src);
        cp16(sb + AQL * 4 + i * 16, Qf4 + QLOFF4 + src);
    }
    for (int i = tid; i < 1024; i += 512) {
        int rbl = i >> 8, j = i & 255;
        size_t srcK = ((size_t)(b * 128 + 0 * 4 + rbl) * 16 + h) * 256 + j;
        cp16(sb + AKST(0) * 4 + i * 16, Kf4 + srcK);
        cp16(sb + (AKST(0) + 4096) * 4 + i * 16, Kf4 + KLOFF4 + srcK);
        cp16(sb + AVST(0) * 4 + i * 16, VF4 + srcK);
        cp16(sb + (AVST(0) + 4096) * 4 + i * 16, VF4 + VLOFF4 + srcK);
    }
    if (tid < 16) cp16(sb + AMSK * 4 + tid * 16, mb + tid * 4);
    CPCOMMIT();

    float m1 = -3.402823466e38f, m2 = -3.402823466e38f;
    float l1 = 0.f, l2 = 0.f;
    float o[8][4];
#pragma unroll
    for (int nt = 0; nt < 8; nt++)
#pragma unroll
        for (int q = 0; q < 4; q++) o[nt][q] = 0.f;

    const int nkt = 2 * qt + 2;
    for (int kt = 0; kt < nkt; kt++) {
        const int s = kt & 1;
        const int k0 = kt * 64;
        CPWAIT0();          // stage(kt) (+Q on kt=0) landed
        __syncthreads();    // all warps past prev iter's buffer reads

        // Prefetch stage(kt+1) into the other buffer — overlaps compute below
        if (kt + 1 < nkt) {
            const int sn = s ^ 1, ktn = kt + 1;
            for (int i = tid; i < 1024; i += 512) {
                int rbl = i >> 8, j = i & 255;
                size_t srcK = ((size_t)(b * 128 + ktn * 4 + rbl) * 16 + h) * 256 + j;
                cp16(sb + AKST(sn) * 4 + i * 16, Kf4 + srcK);
                cp16(sb + (AKST(sn) + 4096) * 4 + i * 16, Kf4 + KLOFF4 + srcK);
                cp16(sb + AVST(sn) * 4 + i * 16, VF4 + srcK);
                cp16(sb + (AVST(sn) + 4096) * 4 + i * 16, VF4 + VLOFF4 + srcK);
            }
            if (tid < 16) cp16(sb + (AMSK + 64) * 4 - s * 256 + tid * 16,
                               mb + ktn * 64 + tid * 4);
        }
        CPCOMMIT();

        const int AK_ = AKST(s);
        const int AV_ = AVST(s);

        // QK: dual accumulation chains
        float sc[4][4], scB[4][4];
#pragma unroll
        for (int nt = 0; nt < 4; nt++)
#pragma unroll
            for (int q = 0; q < 4; q++) { sc[nt][q] = 0.f; scB[nt][q] = 0.f; }

#pragma unroll
        for (int ks = 0; ks < 8; ks++) {
            uint4 ahv = *(const uint4*)&smu[AQ + ((qb * 8 + ks) * 32 + lane) * 4];
            uint4 alv = *(const uint4*)&smu[AQL + ((qb * 8 + ks) * 32 + lane) * 4];
            uint32_t ah[4] = {ahv.x, ahv.y, ahv.z, ahv.w};
            uint32_t al[4] = {alv.x, alv.y, alv.z, alv.w};
            float (*acc)[4] = (ks < 4) ? sc : scB;
#pragma unroll
            for (int nt = 0; nt < 4; nt++) {
                const int ntg = dh * 4 + nt;
                const int base = AK_ + (((ntg >> 1) * 8 + ks) * 2 + (ntg & 1)) * 64 + lane * 2;
                uint2 kh = *(const uint2*)&smu[base];
                uint2 kl = *(const uint2*)&smu[base + 4096];
                mma_bf16_16x8x16(acc[nt], ah, kh.x, kh.y);
                mma_bf16_16x8x16(acc[nt], ah, kl.x, kl.y);
                mma_bf16_16x8x16(acc[nt], al, kh.x, kh.y);
            }
        }
#pragma unroll
        for (int nt = 0; nt < 4; nt++)
#pragma unroll
            for (int q = 0; q < 4; q++) sc[nt][q] += scB[nt][q];

        // Mask + scale + per-half tile max
        float tm1 = -3.402823466e38f, tm2 = -3.402823466e38f;
#pragma unroll
        for (int nt = 0; nt < 4; nt++) {
#pragma unroll
            for (int jj = 0; jj < 2; jj++) {
                const int col = dh * 32 + nt * 8 + tig * 2 + jj;
                const int jg = k0 + col;
                const bool ok = (maskS[s * 64 + col] != 0);
                float s0 = (ok && jg <= q0 + r1) ? sc[nt][jj] * SCALE : NEGV;
                float s1 = (ok && jg <= q0 + r2) ? sc[nt][2 + jj] * SCALE : NEGV;
                sc[nt][jj] = s0; sc[nt][2 + jj] = s1;
                tm1 = fmaxf(tm1, s0); tm2 = fmaxf(tm2, s1);
            }
        }
        tm1 = fmaxf(tm1, __shfl_xor_sync(0xffffffffu, tm1, 1));
        tm1 = fmaxf(tm1, __shfl_xor_sync(0xffffffffu, tm1, 2));
        tm2 = fmaxf(tm2, __shfl_xor_sync(0xffffffffu, tm2, 1));
        tm2 = fmaxf(tm2, __shfl_xor_sync(0xffffffffu, tm2, 2));
        if (tig == 0) { pmxF[dh * 128 + r1] = tm1; pmxF[dh * 128 + r2] = tm2; }
        __syncthreads();  // pmx ready; K(s) reads done -> region reusable for P

        const float mn1 = fmaxf(m1, fmaxf(pmxF[r1], pmxF[128 + r1]));
        const float mn2 = fmaxf(m2, fmaxf(pmxF[r2], pmxF[128 + r2]));
        const float c1 = fexp(m1 - mn1), c2 = fexp(m2 - mn2);
        m1 = mn1; m2 = mn2;

        float s1sum = 0.f, s2sum = 0.f;
#pragma unroll
        for (int nt = 0; nt < 4; nt++) {
            sc[nt][0] = fexp(sc[nt][0] - mn1);
            sc[nt][1] = fexp(sc[nt][1] - mn1);
            sc[nt][2] = fexp(sc[nt][2] - mn2);
            sc[nt][3] = fexp(sc[nt][3] - mn2);
            s1sum += sc[nt][0] + sc[nt][1];
            s2sum += sc[nt][2] + sc[nt][3];
        }
        s1sum += __shfl_xor_sync(0xffffffffu, s1sum, 1);
        s1sum += __shfl_xor_sync(0xffffffffu, s1sum, 2);
        s2sum += __shfl_xor_sync(0xffffffffu, s2sum, 1);
        s2sum += __shfl_xor_sync(0xffffffffu, s2sum, 2);
        if (tig == 0) { plsF[dh * 128 + r1] = s1sum; plsF[dh * 128 + r2] = s2sum; }

        // Write P A-frags into retired K(s) region (hi at AK_, lo at AK_+4096)
#pragma unroll
        for (int t = 0; t < 2; t++) {
            const int ks2 = dh * 2 + t;
            uint32_t h0, l0, h1, l1u, h2, l2u, h3, l3;
            split2(sc[2 * t][0], sc[2 * t][1], h0, l0);
            split2(sc[2 * t][2], sc[2 * t][3], h1, l1u);
            split2(sc[2 * t + 1][0], sc[2 * t + 1][1], h2, l2u);
            split2(sc[2 * t + 1][2], sc[2 * t + 1][3], h3, l3);
            const int idx = ((qb * 4 + ks2) * 32 + lane) * 4;
            *(uint4*)&smu[AK_ + idx] = make_uint4(h0, h1, h2, h3);
            *(uint4*)&smu[AK_ + 4096 + idx] = make_uint4(l0, l1u, l2u, l3);
        }
        __syncthreads();  // P + pls visible

        l1 = l1 * c1 + plsF[r1] + plsF[128 + r1];
        l2 = l2 * c2 + plsF[r2] + plsF[128 + r2];

#pragma unroll
        for (int nt = 0; nt < 8; nt++) {
            o[nt][0] *= c1; o[nt][1] *= c1; o[nt][2] *= c2; o[nt][3] *= c2;
        }

        // PV: A = P frags, B = pre-split V frags
#pragma unroll
        for (int ks2 = 0; ks2 < 4; ks2++) {
            const int idx = ((qb * 4 + ks2) * 32 + lane) * 4;
            uint4 phv = *(const uint4*)&smu[AK_ + idx];
            uint4 plv = *(const uint4*)&smu[AK_ + 4096 + idx];
            uint32_t ph[4] = {phv.x, phv.y, phv.z, phv.w};
            uint32_t pl[4] = {plv.x, plv.y, plv.z, plv.w};
#pragma unroll
            for (int nt = 0; nt < 8; nt++) {
                const int vi = AV_ + ks2 * 1024 + (dh * 8 + nt) * 64 + lane * 2;
                uint2 vh = *(const uint2*)&smu[vi];
                uint2 vl = *(const uint2*)&smu[vi + 4096];
                mma_bf16_16x8x16(o[nt], ph, vh.x, vh.y);
                mma_bf16_16x8x16(o[nt], ph, vl.x, vl.y);
                mma_bf16_16x8x16(o[nt], pl, vh.x, vh.y);
            }
        }
    }

    // Epilogue
    const float inv1 = 1.f / l1, inv2 = 1.f / l2;
    const bool dead1 = m1 < -1e8f, dead2 = m2 < -1e8f;
    const float* vm = vmean + ((size_t)b * HDIM + h) * DKDIM;
    float* O1 = Og + ((size_t)b * SDIM + q0 + r1) * DDIM + h * DKDIM;
    float* O2 = Og + ((size_t)b * SDIM + q0 + r2) * DDIM + h * DKDIM;
#pragma unroll
    for (int nt = 0; nt < 8; nt++) {
        const int d = dh * 64 + nt * 8 + tig * 2;
        float2 u1 = dead1 ? make_float2(vm[d], vm[d + 1])
                          : make_float2(o[nt][0] * inv1, o[nt][1] * inv1);
        float2 u2 = dead2 ? make_float2(vm[d], vm[d + 1])
                          : make_float2(o[nt][2] * inv2, o[nt][3] * inv2);
        *(float2*)(O1 + d) = u1;
        *(float2*)(O2 + d) = u2;
    }
}

// ---------------------------------------------------------------------------
extern "C" void kernel_launch(void* const* d_in, const int* in_sizes, int n_in,
                              void* d_out, int out_size)
{
    const float* x    = (const float*)d_in[0];
    const int*   mask = (const int*)d_in[1];
    const float* wq   = (const float*)d_in[2];
    const float* wk   = (const float*)d_in[3];
    const float* wv   = (const float*)d_in[4];
    const float* wo   = (const float*)d_in[5];
    float* out = (float*)d_out;

    float *pQ, *pK, *pV, *pAtt, *pVm;
    uint32_t* pVF;
    cudaGetSymbolAddress((void**)&pQ, g_Q);
    cudaGetSymbolAddress((void**)&pK, g_K);
    cudaGetSymbolAddress((void**)&pV, g_V);
    cudaGetSymbolAddress((void**)&pVF, g_VF);
    cudaGetSymbolAddress((void**)&pAtt, g_att);
    cudaGetSymbolAddress((void**)&pVm, g_vmean);

    cudaFuncSetAttribute(attn_mma_kernel, cudaFuncAttributeMaxDynamicSharedMemorySize,
                         ATT_SMEM_BYTES);

    dim3 gg(GN / 128, MDIM / 128);  // (16, 64)
    gemm_mma_kernel<<<gg, 256>>>(x, wq, pQ, 1);   // Q -> A-frag layout
    gemm_mma_kernel<<<gg, 256>>>(x, wk, pK, 2);   // K -> B-frag layout
    gemm_mma_kernel<<<gg, 256>>>(x, wv, pV, 0);   // V fp32

    vmean_kernel<<<BDIM * HDIM, 1024>>>(pV, pVm);
    vsplit_kernel<<<dim3(HDIM, SDIM / 16, BDIM), 128>>>(pV, pVF);

    attn_mma_kernel<<<dim3(SDIM / 128, HDIM, BDIM), 512, ATT_SMEM_BYTES>>>(
        (const uint4*)pQ, (const uint4*)pK, (const uint4*)pVF, mask, pVm, pAtt);

    gemm_mma_kernel<<<gg, 256>>>(pAtt, wo, out, 0);
}